// round 3
// baseline (speedup 1.0000x reference)
#include <cuda_runtime.h>
#include <cuda_fp16.h>
#include <cstdint>
#include <cstring>

// ============================================================================
// Problem constants
// ============================================================================
static constexpr int NROWS   = 1048576;
static constexpr int H       = 128;
static constexpr int L       = 16;
static constexpr int THREADS = 256;
static constexpr int TILE_M  = 128;

static constexpr float W_SCALE = 1024.0f;
static constexpr float W_INV   = 1.0f / 1024.0f;

// Padded row: 128 halves + 8 pad = 136 halves = 272 bytes (68 words ≡ 4 mod 32
// banks per row -> conflict-free ldmatrix / epilogue stores).
static constexpr int SROW   = 272;
static constexpr int WTILE  = 128 * SROW;       // one 128x128 fp16 matrix: 34816 B
static constexpr int WLAYER = 2 * WTILE;        // hi + lo: 69632 B

// SMEM layout (byte offsets)
static constexpr int OFF_HHI  = 0;
static constexpr int OFF_HLO  = OFF_HHI + TILE_M * SROW;   // 34816
static constexpr int OFF_W    = OFF_HLO + TILE_M * SROW;   // 69632 (2 buffers)
static constexpr int OFF_BIAS = OFF_W + 2 * WLAYER;        // 208896
static constexpr int OFF_WOUT = OFF_BIAS + L * H * 4;      // 217088
static constexpr int OFF_BOUT = OFF_WOUT + 2 * H * 4;      // 218112
static constexpr int SMEM_BYTES = OFF_BOUT + 16;           // 218128

// fp32 reuse of the h region for the final projection (stride 133 words: 5t+i
// mod 32 -> conflict-free column reads)
static constexpr int F32_STRIDE = 133;

// Pre-split (x 2^10), pre-padded fp16 weight images: per layer [hi | lo],
// each 128 rows x 272B, row n holds W[n][k] halves at n*SROW + 2k.
__device__ __align__(128) unsigned char g_w[(size_t)L * WLAYER];

// ============================================================================
// PTX helpers
// ============================================================================
__device__ __forceinline__ uint32_t smem_to_u32(const void* p) {
    uint32_t a;
    asm("{ .reg .u64 t; cvta.to.shared.u64 t, %1; cvt.u32.u64 %0, t; }"
        : "=r"(a) : "l"(p));
    return a;
}

#define LDSM_X4(r, addr) \
    asm volatile("ldmatrix.sync.aligned.m8n8.x4.shared.b16 {%0,%1,%2,%3}, [%4];" \
        : "=r"((r)[0]), "=r"((r)[1]), "=r"((r)[2]), "=r"((r)[3]) : "r"(addr))

#define MMA16816(c, a, b0, b1) \
    asm volatile("mma.sync.aligned.m16n8k16.row.col.f32.f16.f16.f32 " \
        "{%0,%1,%2,%3}, {%4,%5,%6,%7}, {%8,%9}, {%0,%1,%2,%3};" \
        : "+f"((c)[0]), "+f"((c)[1]), "+f"((c)[2]), "+f"((c)[3]) \
        : "r"((a)[0]), "r"((a)[1]), "r"((a)[2]), "r"((a)[3]), "r"(b0), "r"(b1))

__device__ __forceinline__ void cp16(uint32_t dst, const void* src) {
    asm volatile("cp.async.cg.shared.global [%0], [%1], 16;" :: "r"(dst), "l"(src));
}
#define CP_COMMIT() asm volatile("cp.async.commit_group;" ::: "memory")
#define CP_WAIT1()  asm volatile("cp.async.wait_group 1;" ::: "memory")

__device__ __forceinline__ uint32_t h2u(__half2 h) {
    uint32_t u; memcpy(&u, &h, 4); return u;
}

// split (v0,v1) into hi fp16x2 + residual fp16x2
__device__ __forceinline__ void split2(float v0, float v1, uint32_t& hi, uint32_t& lo) {
    __half2 h = __floats2half2_rn(v0, v1);
    float2 f = __half22float2(h);
    __half2 e = __floats2half2_rn(v0 - f.x, v1 - f.y);
    hi = h2u(h); lo = h2u(e);
}

// ============================================================================
// Prep kernel: W*2^10 -> hi/lo fp16, padded [n][k] layout per layer
// ============================================================================
__global__ void prep_w_kernel(const float* __restrict__ W) {
    const int l = blockIdx.x;
    const float* Wl = W + (size_t)l * H * H;
    unsigned char* hi = g_w + (size_t)l * WLAYER;
    unsigned char* lo = hi + WTILE;
    for (int i = threadIdx.x; i < H * H; i += blockDim.x) {
        const int n = i >> 7, k = i & 127;
        const float w = Wl[i] * W_SCALE;
        const __half h = __float2half_rn(w);
        const __half e = __float2half_rn(w - __half2float(h));
        const int off = n * SROW + 2 * k;
        *(__half*)(hi + off) = h;
        *(__half*)(lo + off) = e;
    }
}

// issue cp.async for one layer's hi+lo tiles into SMEM buffer
__device__ __forceinline__ void load_w(uint32_t dst_smem, int l, int tid) {
    const unsigned char* src = g_w + (size_t)l * WLAYER;
#pragma unroll
    for (int i = 0; i < 17; i++) {              // 17*256*16 = 69632
        const int off = (tid + i * THREADS) * 16;
        cp16(dst_smem + off, src + off);
    }
}

// ============================================================================
// Main fused MLP kernel (HMMA path, fp16 hi/lo x 3 passes)
// ============================================================================
__global__ void __launch_bounds__(THREADS, 1)
mlp_main(const float* __restrict__ x, const float* __restrict__ b,
         const float* __restrict__ Wout, const float* __restrict__ bout,
         float* __restrict__ out) {
    extern __shared__ unsigned char smem[];
    const uint32_t sb = smem_to_u32(smem);
    const int tid = threadIdx.x;
    const int lane = tid & 31;
    const int wid = tid >> 5;
    const int wm = wid & 3;      // 4 m-warps x 32 rows
    const int wn = wid >> 2;     // 2 n-warps x 64 cols

    // ---- stage fixed tables ----
    {
        const float4* bs = (const float4*)b;               // 512 float4
        float4* bd = (float4*)(smem + OFF_BIAS);
        bd[tid] = bs[tid];
        bd[tid + 256] = bs[tid + 256];
        if (tid < 64) ((float4*)(smem + OFF_WOUT))[tid] = ((const float4*)Wout)[tid];
        if (tid < 2)  ((float*)(smem + OFF_BOUT))[tid] = bout[tid];
    }

    // ---- kick W[0] copy ----
    load_w(sb + OFF_W, 0, tid);
    CP_COMMIT();

    // ---- prologue: x -> h hi/lo in SMEM ----
    {
        const float4* xs = (const float4*)(x + (size_t)blockIdx.x * TILE_M * H);
#pragma unroll
        for (int i = 0; i < 16; i++) {
            const int idx = tid + i * THREADS;     // 0..4095
            const int r = idx >> 5, c = idx & 31;  // row, float4-within-row
            const float4 v = xs[idx];
            uint32_t hi0, lo0, hi1, lo1;
            split2(v.x, v.y, hi0, lo0);
            split2(v.z, v.w, hi1, lo1);
            const int off = r * SROW + c * 8;
            *(uint2*)(smem + OFF_HHI + off) = make_uint2(hi0, hi1);
            *(uint2*)(smem + OFF_HLO + off) = make_uint2(lo0, lo1);
        }
    }

    // ---- per-thread ldmatrix address roles ----
    const int arow = (lane & 7) | (((lane >> 3) & 1) << 3);  // 0..15
    const int achk = lane >> 4;                              // 0..1
    const uint32_t aoff = (uint32_t)((32 * wm + arow) * SROW + achk * 16);

    const int bg = lane >> 3;
    const int bn = ((bg >> 1) << 3) | (lane & 7);            // 0..15 in n-group
    const int bchk = bg & 1;
    const uint32_t boff = (uint32_t)((64 * wn + bn) * SROW + bchk * 16);

    // epilogue roles
    const int er = 32 * wm + (lane >> 2);          // + mt*16 (+8 for c2/c3)
    const int ec = 64 * wn + 2 * (lane & 3);       // + nt*8

#pragma unroll 1
    for (int l = 0; l < L; l++) {
        if (l + 1 < L) load_w(sb + OFF_W + ((l + 1) & 1) * WLAYER, l + 1, tid);
        CP_COMMIT();
        CP_WAIT1();              // W[l] resident
        __syncthreads();         // W + h visible to all warps

        const uint32_t hhi = sb + OFF_HHI + aoff;
        const uint32_t hlo = sb + OFF_HLO + aoff;
        const uint32_t wb  = sb + OFF_W + (uint32_t)(l & 1) * WLAYER;
        const uint32_t whi = wb + boff;
        const uint32_t wlo = wb + WTILE + boff;

        float acc[2][8][4];
#pragma unroll
        for (int mt = 0; mt < 2; mt++)
#pragma unroll
            for (int nt = 0; nt < 8; nt++)
#pragma unroll
                for (int q = 0; q < 4; q++) acc[mt][nt][q] = 0.f;

#pragma unroll
        for (int ks = 0; ks < 8; ks++) {
            const uint32_t kb = ks * 32;
            uint32_t ahi[2][4], alo[2][4], bhi[4][4], blo[4][4];
#pragma unroll
            for (int mt = 0; mt < 2; mt++) {
                LDSM_X4(ahi[mt], hhi + mt * (16 * SROW) + kb);
                LDSM_X4(alo[mt], hlo + mt * (16 * SROW) + kb);
            }
#pragma unroll
            for (int ng = 0; ng < 4; ng++) {
                LDSM_X4(bhi[ng], whi + ng * (16 * SROW) + kb);
                LDSM_X4(blo[ng], wlo + ng * (16 * SROW) + kb);
            }
#pragma unroll
            for (int mt = 0; mt < 2; mt++) {
#pragma unroll
                for (int ng = 0; ng < 4; ng++) {
                    MMA16816(acc[mt][2 * ng],     ahi[mt], bhi[ng][0], bhi[ng][1]);
                    MMA16816(acc[mt][2 * ng],     alo[mt], bhi[ng][0], bhi[ng][1]);
                    MMA16816(acc[mt][2 * ng],     ahi[mt], blo[ng][0], blo[ng][1]);
                    MMA16816(acc[mt][2 * ng + 1], ahi[mt], bhi[ng][2], bhi[ng][3]);
                    MMA16816(acc[mt][2 * ng + 1], alo[mt], bhi[ng][2], bhi[ng][3]);
                    MMA16816(acc[mt][2 * ng + 1], ahi[mt], blo[ng][2], blo[ng][3]);
                }
            }
        }

        __syncthreads();         // all h reads done before overwrite

        // bias values for this thread's columns
        float lb[16];
#pragma unroll
        for (int nt = 0; nt < 8; nt++) {
            const float2 t = *(const float2*)(smem + OFF_BIAS + (l * H + ec + 8 * nt) * 4);
            lb[2 * nt] = t.x; lb[2 * nt + 1] = t.y;
        }

        if (l < L - 1) {
#pragma unroll
            for (int mt = 0; mt < 2; mt++) {
#pragma unroll
                for (int nt = 0; nt < 8; nt++) {
                    const float v0 = fmaxf(fmaf(acc[mt][nt][0], W_INV, lb[2 * nt]),     0.f);
                    const float v1 = fmaxf(fmaf(acc[mt][nt][1], W_INV, lb[2 * nt + 1]), 0.f);
                    const float v2 = fmaxf(fmaf(acc[mt][nt][2], W_INV, lb[2 * nt]),     0.f);
                    const float v3 = fmaxf(fmaf(acc[mt][nt][3], W_INV, lb[2 * nt + 1]), 0.f);
                    uint32_t hi01, lo01, hi23, lo23;
                    split2(v0, v1, hi01, lo01);
                    split2(v2, v3, hi23, lo23);
                    const int r = er + mt * 16;
                    const int c = ec + nt * 8;
                    *(uint32_t*)(smem + OFF_HHI + r * SROW + c * 2)        = hi01;
                    *(uint32_t*)(smem + OFF_HLO + r * SROW + c * 2)        = lo01;
                    *(uint32_t*)(smem + OFF_HHI + (r + 8) * SROW + c * 2)  = hi23;
                    *(uint32_t*)(smem + OFF_HLO + (r + 8) * SROW + c * 2)  = lo23;
                }
            }
        } else {
            // final layer: store relu(h) as fp32, stride-133 words
            float* hf = (float*)(smem + OFF_HHI);
#pragma unroll
            for (int mt = 0; mt < 2; mt++) {
#pragma unroll
                for (int nt = 0; nt < 8; nt++) {
                    const float v0 = fmaxf(fmaf(acc[mt][nt][0], W_INV, lb[2 * nt]),     0.f);
                    const float v1 = fmaxf(fmaf(acc[mt][nt][1], W_INV, lb[2 * nt + 1]), 0.f);
                    const float v2 = fmaxf(fmaf(acc[mt][nt][2], W_INV, lb[2 * nt]),     0.f);
                    const float v3 = fmaxf(fmaf(acc[mt][nt][3], W_INV, lb[2 * nt + 1]), 0.f);
                    const int r = er + mt * 16;
                    const int c = ec + nt * 8;
                    hf[r * F32_STRIDE + c]           = v0;
                    hf[r * F32_STRIDE + c + 1]       = v1;
                    hf[(r + 8) * F32_STRIDE + c]     = v2;
                    hf[(r + 8) * F32_STRIDE + c + 1] = v3;
                }
            }
        }
    }

    __syncthreads();

    // ---- final projection: relu_h[128] @ Wout.T + bout ----
    if (tid < TILE_M) {
        const float* hf = (const float*)(smem + OFF_HHI) + tid * F32_STRIDE;
        const float* wo = (const float*)(smem + OFF_WOUT);
        const float* bo = (const float*)(smem + OFF_BOUT);
        float o0 = bo[0], o1 = bo[1];
#pragma unroll
        for (int k = 0; k < H; k++) {
            const float v = hf[k];
            o0 = fmaf(v, wo[k], o0);
            o1 = fmaf(v, wo[H + k], o1);
        }
        ((float2*)out)[(size_t)blockIdx.x * TILE_M + tid] = make_float2(o0, o1);
    }
}

// ============================================================================
// Launch
// ============================================================================
extern "C" void kernel_launch(void* const* d_in, const int* in_sizes, int n_in,
                              void* d_out, int out_size) {
    const float* x    = (const float*)d_in[0];
    const float* W    = (const float*)d_in[1];
    const float* b    = (const float*)d_in[2];
    const float* Wout = (const float*)d_in[3];
    const float* bout = (const float*)d_in[4];
    float* out = (float*)d_out;

    prep_w_kernel<<<L, 256>>>(W);

    cudaFuncSetAttribute(mlp_main, cudaFuncAttributeMaxDynamicSharedMemorySize, SMEM_BYTES);
    mlp_main<<<NROWS / TILE_M, THREADS, SMEM_BYTES>>>(x, b, Wout, bout, out);
}

// round 4
// speedup vs baseline: 1.4086x; 1.4086x over previous
#include <cuda_runtime.h>
#include <cuda_fp16.h>
#include <cstdint>
#include <cstring>

// ============================================================================
// Problem constants
// ============================================================================
static constexpr int NROWS   = 1048576;
static constexpr int H       = 128;
static constexpr int L       = 16;
static constexpr int THREADS = 256;
static constexpr int ROWS    = 256;    // per CTA: two 128-row tiles

// Padded row: 128 halves + 8 pad = 272 bytes -> conflict-free ldmatrix.
static constexpr int SROW  = 272;
static constexpr int WTILE = 128 * SROW;        // one 128x128 fp16 matrix: 34816 B

// SMEM layout (byte offsets). Each h region = hi tile + lo tile.
static constexpr int OFF_H0   = 0;                       // 2*34816
static constexpr int OFF_H1   = OFF_H0 + 2 * WTILE;      // 69632
static constexpr int OFF_W    = OFF_H1 + 2 * WTILE;      // 139264 (2 buffers)
static constexpr int OFF_BIAS = OFF_W + 2 * WTILE;       // 208896
static constexpr int OFF_WOUT = OFF_BIAS + L * H * 4;    // 217088
static constexpr int OFF_BOUT = OFF_WOUT + 2 * H * 4;    // 218112
static constexpr int SMEM_BYTES = OFF_BOUT + 16;         // 218128

// fp32 reuse of h regions for the final projection (stride 133 words)
static constexpr int F32_STRIDE = 133;

// Plain fp16 W image, padded [n][k] rows (row n: W[n][k] at n*SROW + 2k)
__device__ __align__(128) unsigned char g_w[(size_t)L * WTILE];

// ============================================================================
// PTX helpers
// ============================================================================
__device__ __forceinline__ uint32_t smem_to_u32(const void* p) {
    uint32_t a;
    asm("{ .reg .u64 t; cvta.to.shared.u64 t, %1; cvt.u32.u64 %0, t; }"
        : "=r"(a) : "l"(p));
    return a;
}

#define LDSM_X4(r, addr) \
    asm volatile("ldmatrix.sync.aligned.m8n8.x4.shared.b16 {%0,%1,%2,%3}, [%4];" \
        : "=r"((r)[0]), "=r"((r)[1]), "=r"((r)[2]), "=r"((r)[3]) : "r"(addr))

#define MMA16816(c, a, b0, b1) \
    asm volatile("mma.sync.aligned.m16n8k16.row.col.f32.f16.f16.f32 " \
        "{%0,%1,%2,%3}, {%4,%5,%6,%7}, {%8,%9}, {%0,%1,%2,%3};" \
        : "+f"((c)[0]), "+f"((c)[1]), "+f"((c)[2]), "+f"((c)[3]) \
        : "r"((a)[0]), "r"((a)[1]), "r"((a)[2]), "r"((a)[3]), "r"(b0), "r"(b1))

__device__ __forceinline__ void cp16(uint32_t dst, const void* src) {
    asm volatile("cp.async.cg.shared.global [%0], [%1], 16;" :: "r"(dst), "l"(src));
}
#define CP_COMMIT() asm volatile("cp.async.commit_group;" ::: "memory")
#define CP_WAIT0()  asm volatile("cp.async.wait_group 0;" ::: "memory")

__device__ __forceinline__ uint32_t h2u(__half2 h) {
    uint32_t u; memcpy(&u, &h, 4); return u;
}

// split (v0,v1) into hi fp16x2 + residual fp16x2
__device__ __forceinline__ void split2(float v0, float v1, uint32_t& hi, uint32_t& lo) {
    __half2 h = __floats2half2_rn(v0, v1);
    float2 f = __half22float2(h);
    __half2 e = __floats2half2_rn(v0 - f.x, v1 - f.y);
    hi = h2u(h); lo = h2u(e);
}

// ============================================================================
// Prep kernel: W -> fp16, padded [n][k] layout per layer
// ============================================================================
__global__ void prep_w_kernel(const float* __restrict__ W) {
    const int l = blockIdx.x;
    const float* Wl = W + (size_t)l * H * H;
    unsigned char* dst = g_w + (size_t)l * WTILE;
    for (int i = threadIdx.x; i < H * H; i += blockDim.x) {
        const int n = i >> 7, k = i & 127;
        *(__half*)(dst + n * SROW + 2 * k) = __float2half_rn(Wl[i]);
    }
}

// issue cp.async for one layer's W tile (34816 B = 2176 x 16B)
__device__ __forceinline__ void load_w(uint32_t dst_smem, int l, int tid) {
    const unsigned char* src = g_w + (size_t)l * WTILE;
#pragma unroll
    for (int i = 0; i < 9; i++) {
        const int idx = tid + i * THREADS;
        if (idx < WTILE / 16) cp16(dst_smem + idx * 16, src + idx * 16);
    }
}

// ============================================================================
// MMA for one 128-row tile: acc = (h_hi + h_lo) @ W_l^T   (2 fp16 passes)
// ============================================================================
__device__ __forceinline__ void mma_tile(float acc[2][8][4],
                                         uint32_t hhi, uint32_t hlo, uint32_t wb) {
#pragma unroll
    for (int mt = 0; mt < 2; mt++)
#pragma unroll
        for (int nt = 0; nt < 8; nt++)
#pragma unroll
            for (int q = 0; q < 4; q++) acc[mt][nt][q] = 0.f;

#pragma unroll
    for (int ks = 0; ks < 8; ks++) {
        const uint32_t kb = ks * 32;
        uint32_t ahi[2][4], alo[2][4], bf[4][4];
#pragma unroll
        for (int mt = 0; mt < 2; mt++) {
            LDSM_X4(ahi[mt], hhi + mt * (16 * SROW) + kb);
            LDSM_X4(alo[mt], hlo + mt * (16 * SROW) + kb);
        }
#pragma unroll
        for (int ng = 0; ng < 4; ng++)
            LDSM_X4(bf[ng], wb + ng * (16 * SROW) + kb);

        // pass 1: hi (same-acc dependency distance = 16 MMAs)
#pragma unroll
        for (int mt = 0; mt < 2; mt++)
#pragma unroll
            for (int ng = 0; ng < 4; ng++) {
                MMA16816(acc[mt][2 * ng],     ahi[mt], bf[ng][0], bf[ng][1]);
                MMA16816(acc[mt][2 * ng + 1], ahi[mt], bf[ng][2], bf[ng][3]);
            }
        // pass 2: lo residual
#pragma unroll
        for (int mt = 0; mt < 2; mt++)
#pragma unroll
            for (int ng = 0; ng < 4; ng++) {
                MMA16816(acc[mt][2 * ng],     alo[mt], bf[ng][0], bf[ng][1]);
                MMA16816(acc[mt][2 * ng + 1], alo[mt], bf[ng][2], bf[ng][3]);
            }
    }
}

// ============================================================================
// Epilogues
// ============================================================================
__device__ __forceinline__ void epi_split(const float acc[2][8][4],
                                          const float* __restrict__ bl,
                                          unsigned char* hbase, int er, int ec) {
#pragma unroll
    for (int mt = 0; mt < 2; mt++)
#pragma unroll
        for (int nt = 0; nt < 8; nt++) {
            const float b0 = bl[ec + 8 * nt], b1 = bl[ec + 8 * nt + 1];
            const float v0 = fmaxf(acc[mt][nt][0] + b0, 0.f);
            const float v1 = fmaxf(acc[mt][nt][1] + b1, 0.f);
            const float v2 = fmaxf(acc[mt][nt][2] + b0, 0.f);
            const float v3 = fmaxf(acc[mt][nt][3] + b1, 0.f);
            uint32_t hi01, lo01, hi23, lo23;
            split2(v0, v1, hi01, lo01);
            split2(v2, v3, hi23, lo23);
            const int r = er + mt * 16;
            const int c = ec + nt * 8;
            *(uint32_t*)(hbase + r * SROW + c * 2)               = hi01;
            *(uint32_t*)(hbase + WTILE + r * SROW + c * 2)       = lo01;
            *(uint32_t*)(hbase + (r + 8) * SROW + c * 2)         = hi23;
            *(uint32_t*)(hbase + WTILE + (r + 8) * SROW + c * 2) = lo23;
        }
}

__device__ __forceinline__ void epi_final(const float acc[2][8][4],
                                          const float* __restrict__ bl,
                                          float* hf, int er, int ec) {
#pragma unroll
    for (int mt = 0; mt < 2; mt++)
#pragma unroll
        for (int nt = 0; nt < 8; nt++) {
            const float b0 = bl[ec + 8 * nt], b1 = bl[ec + 8 * nt + 1];
            const int r = er + mt * 16;
            const int c = ec + nt * 8;
            hf[r * F32_STRIDE + c]           = fmaxf(acc[mt][nt][0] + b0, 0.f);
            hf[r * F32_STRIDE + c + 1]       = fmaxf(acc[mt][nt][1] + b1, 0.f);
            hf[(r + 8) * F32_STRIDE + c]     = fmaxf(acc[mt][nt][2] + b0, 0.f);
            hf[(r + 8) * F32_STRIDE + c + 1] = fmaxf(acc[mt][nt][3] + b1, 0.f);
        }
}

// ============================================================================
// Main fused MLP kernel: 2 tiles x 128 rows, phase-interleaved MMA/epilogue
// ============================================================================
__global__ void __launch_bounds__(THREADS, 1)
mlp_main(const float* __restrict__ x, const float* __restrict__ b,
         const float* __restrict__ Wout, const float* __restrict__ bout,
         float* __restrict__ out) {
    extern __shared__ unsigned char smem[];
    const uint32_t sb = smem_to_u32(smem);
    const int tid = threadIdx.x;
    const int lane = tid & 31;
    const int wid = tid >> 5;
    const int wm = wid & 3;      // 4 m-warps x 32 rows
    const int wn = wid >> 2;     // 2 n-warps x 64 cols

    // ---- stage fixed tables ----
    {
        const float4* bs = (const float4*)b;
        float4* bd = (float4*)(smem + OFF_BIAS);
        bd[tid] = bs[tid];
        bd[tid + 256] = bs[tid + 256];
        if (tid < 64) ((float4*)(smem + OFF_WOUT))[tid] = ((const float4*)Wout)[tid];
        if (tid < 2)  ((float*)(smem + OFF_BOUT))[tid] = bout[tid];
    }

    // ---- kick W[0] copy ----
    load_w(sb + OFF_W, 0, tid);
    CP_COMMIT();

    // ---- prologue: x -> h0/h1 hi/lo in SMEM ----
    {
        const float4* xs = (const float4*)(x + (size_t)blockIdx.x * ROWS * H);
#pragma unroll
        for (int i = 0; i < 32; i++) {
            const int idx = tid + i * THREADS;     // 0..8191
            const int r = idx >> 5, c = idx & 31;  // row 0..255, float4 idx
            const float4 v = xs[idx];
            uint32_t hi0, lo0, hi1, lo1;
            split2(v.x, v.y, hi0, lo0);
            split2(v.z, v.w, hi1, lo1);
            unsigned char* hb = smem + (r < 128 ? OFF_H0 : OFF_H1);
            const int off = (r & 127) * SROW + c * 8;
            *(uint2*)(hb + off)         = make_uint2(hi0, hi1);
            *(uint2*)(hb + WTILE + off) = make_uint2(lo0, lo1);
        }
    }

    // ---- per-thread ldmatrix address roles ----
    const int arow = (lane & 7) | (((lane >> 3) & 1) << 3);
    const int achk = lane >> 4;
    const uint32_t aoff = (uint32_t)((32 * wm + arow) * SROW + achk * 16);

    const int bg = lane >> 3;
    const int bn = ((bg >> 1) << 3) | (lane & 7);
    const int bchk = bg & 1;
    const uint32_t boff = (uint32_t)((64 * wn + bn) * SROW + bchk * 16);

    // epilogue roles
    const int er = 32 * wm + (lane >> 2);
    const int ec = 64 * wn + 2 * (lane & 3);

    const float* bias = (const float*)(smem + OFF_BIAS);

    float acc0[2][8][4], acc1[2][8][4];

#pragma unroll 1
    for (int l = 0; l < L; l++) {
        CP_WAIT0();              // W[l] resident (per-thread)
        __syncthreads();         // W + h0 writes visible; h1 reads (prev B) done

        const uint32_t wb = sb + OFF_W + (uint32_t)(l & 1) * WTILE + boff;

        // ---- phase A: MMA tile0(l)  ||  epilogue tile1(l-1) ----
        mma_tile(acc0, sb + OFF_H0 + aoff, sb + OFF_H0 + WTILE + aoff, wb);
        if (l > 0)
            epi_split(acc1, bias + (l - 1) * H, smem + OFF_H1, er, ec);

        __syncthreads();         // h0 reads done; h1 writes visible

        // ---- phase B: prefetch W[l+1]; MMA tile1(l)  ||  epilogue tile0(l) ----
        if (l + 1 < L) {
            load_w(sb + OFF_W + (uint32_t)((l + 1) & 1) * WTILE, l + 1, tid);
            CP_COMMIT();
        }
        mma_tile(acc1, sb + OFF_H1 + aoff, sb + OFF_H1 + WTILE + aoff, wb);
        if (l < L - 1)
            epi_split(acc0, bias + l * H, smem + OFF_H0, er, ec);
        else
            epi_final(acc0, bias + l * H, (float*)(smem + OFF_H0), er, ec);
    }

    __syncthreads();
    epi_final(acc1, bias + (L - 1) * H, (float*)(smem + OFF_H1), er, ec);
    __syncthreads();

    // ---- final projection: relu_h[256] @ Wout.T + bout ----
    {
        const float* hf = (const float*)(smem + (tid < 128 ? OFF_H0 : OFF_H1))
                        + (tid & 127) * F32_STRIDE;
        const float* wo = (const float*)(smem + OFF_WOUT);
        const float* bo = (const float*)(smem + OFF_BOUT);
        float o0 = bo[0], o1 = bo[1];
#pragma unroll
        for (int k = 0; k < H; k++) {
            const float v = hf[k];
            o0 = fmaf(v, wo[k], o0);
            o1 = fmaf(v, wo[H + k], o1);
        }
        ((float2*)out)[(size_t)blockIdx.x * ROWS + tid] = make_float2(o0, o1);
    }
}

// ============================================================================
// Launch
// ============================================================================
extern "C" void kernel_launch(void* const* d_in, const int* in_sizes, int n_in,
                              void* d_out, int out_size) {
    const float* x    = (const float*)d_in[0];
    const float* W    = (const float*)d_in[1];
    const float* b    = (const float*)d_in[2];
    const float* Wout = (const float*)d_in[3];
    const float* bout = (const float*)d_in[4];
    float* out = (float*)d_out;

    prep_w_kernel<<<L, 256>>>(W);

    cudaFuncSetAttribute(mlp_main, cudaFuncAttributeMaxDynamicSharedMemorySize, SMEM_BYTES);
    mlp_main<<<NROWS / ROWS, THREADS, SMEM_BYTES>>>(x, b, Wout, bout, out);
}

// round 5
// speedup vs baseline: 2.4281x; 1.7238x over previous
#include <cuda_runtime.h>
#include <cuda_fp16.h>
#include <cstdint>
#include <cstring>

// ============================================================================
// Problem constants
// ============================================================================
static constexpr int NROWS   = 1048576;
static constexpr int H       = 128;
static constexpr int L       = 16;
static constexpr int THREADS = 256;
static constexpr int ROWS    = 256;    // per CTA: two 128-row tiles

// Padded row: 128 halves + 8 pad = 272 bytes -> conflict-free ldmatrix.
static constexpr int SROW  = 272;
static constexpr int WTILE = 128 * SROW;        // one 128x128 fp16 matrix: 34816 B

// SMEM layout (byte offsets)
static constexpr int OFF_H0   = 0;                       // tile0 h (fp16)
static constexpr int OFF_H1   = OFF_H0 + WTILE;          // 34816 tile1 h
static constexpr int OFF_W    = OFF_H1 + WTILE;          // 69632 (2 buffers)
static constexpr int OFF_BIAS = OFF_W + 2 * WTILE;       // 139264
static constexpr int OFF_WOUT = OFF_BIAS + L * H * 4;    // 147456
static constexpr int OFF_BOUT = OFF_WOUT + 2 * H * 4;    // 148480
static constexpr int SMEM_BYTES = OFF_BOUT + 16;         // 148496

// fp32 final-h layout (stride 133 words -> conflict-free column reads).
// tile0 spans [OFF_H0, OFF_H0+68096) (h0+h1 regions, dead by then);
// tile1 goes into the W double-buffer region (dead after last MMA).
static constexpr int F32_STRIDE = 133;

// Plain fp16 W image, padded [n][k] rows (row n: W[n][k] at n*SROW + 2k)
__device__ __align__(128) unsigned char g_w[(size_t)L * WTILE];

// ============================================================================
// PTX helpers
// ============================================================================
__device__ __forceinline__ uint32_t smem_to_u32(const void* p) {
    uint32_t a;
    asm("{ .reg .u64 t; cvta.to.shared.u64 t, %1; cvt.u32.u64 %0, t; }"
        : "=r"(a) : "l"(p));
    return a;
}

#define LDSM_X4(r, addr) \
    asm volatile("ldmatrix.sync.aligned.m8n8.x4.shared.b16 {%0,%1,%2,%3}, [%4];" \
        : "=r"((r)[0]), "=r"((r)[1]), "=r"((r)[2]), "=r"((r)[3]) : "r"(addr))

#define MMA16816(c, a, b0, b1) \
    asm volatile("mma.sync.aligned.m16n8k16.row.col.f32.f16.f16.f32 " \
        "{%0,%1,%2,%3}, {%4,%5,%6,%7}, {%8,%9}, {%0,%1,%2,%3};" \
        : "+f"((c)[0]), "+f"((c)[1]), "+f"((c)[2]), "+f"((c)[3]) \
        : "r"((a)[0]), "r"((a)[1]), "r"((a)[2]), "r"((a)[3]), "r"(b0), "r"(b1))

__device__ __forceinline__ void cp16(uint32_t dst, const void* src) {
    asm volatile("cp.async.cg.shared.global [%0], [%1], 16;" :: "r"(dst), "l"(src));
}
#define CP_COMMIT() asm volatile("cp.async.commit_group;" ::: "memory")
#define CP_WAIT0()  asm volatile("cp.async.wait_group 0;" ::: "memory")

__device__ __forceinline__ uint32_t h2u(__half2 h) {
    uint32_t u; memcpy(&u, &h, 4); return u;
}

// ============================================================================
// Prep kernel: W -> fp16, padded [n][k] layout per layer
// ============================================================================
__global__ void prep_w_kernel(const float* __restrict__ W) {
    const int l = blockIdx.x;
    const float* Wl = W + (size_t)l * H * H;
    unsigned char* dst = g_w + (size_t)l * WTILE;
    for (int i = threadIdx.x; i < H * H; i += blockDim.x) {
        const int n = i >> 7, k = i & 127;
        *(__half*)(dst + n * SROW + 2 * k) = __float2half_rn(Wl[i]);
    }
}

// issue cp.async for one layer's W tile (34816 B = 2176 x 16B)
__device__ __forceinline__ void load_w(uint32_t dst_smem, int l, int tid) {
    const unsigned char* src = g_w + (size_t)l * WTILE;
#pragma unroll
    for (int i = 0; i < 9; i++) {
        const int idx = tid + i * THREADS;
        if (idx < WTILE / 16) cp16(dst_smem + idx * 16, src + idx * 16);
    }
}

// ============================================================================
// MMA for one 128-row tile: acc = h @ W_l^T   (single fp16 pass)
// ============================================================================
__device__ __forceinline__ void mma_tile(float acc[2][8][4], uint32_t ha, uint32_t wb) {
#pragma unroll
    for (int mt = 0; mt < 2; mt++)
#pragma unroll
        for (int nt = 0; nt < 8; nt++)
#pragma unroll
            for (int q = 0; q < 4; q++) acc[mt][nt][q] = 0.f;

#pragma unroll
    for (int ks = 0; ks < 8; ks++) {
        const uint32_t kb = ks * 32;
        uint32_t af[2][4], bf[4][4];
#pragma unroll
        for (int mt = 0; mt < 2; mt++)
            LDSM_X4(af[mt], ha + mt * (16 * SROW) + kb);
#pragma unroll
        for (int ng = 0; ng < 4; ng++)
            LDSM_X4(bf[ng], wb + ng * (16 * SROW) + kb);

#pragma unroll
        for (int mt = 0; mt < 2; mt++)
#pragma unroll
            for (int ng = 0; ng < 4; ng++) {
                MMA16816(acc[mt][2 * ng],     af[mt], bf[ng][0], bf[ng][1]);
                MMA16816(acc[mt][2 * ng + 1], af[mt], bf[ng][2], bf[ng][3]);
            }
    }
}

// ============================================================================
// Epilogues
// ============================================================================
__device__ __forceinline__ void epi_h(const float acc[2][8][4],
                                      const float* __restrict__ bl,
                                      unsigned char* hbase, int er, int ec) {
#pragma unroll
    for (int mt = 0; mt < 2; mt++)
#pragma unroll
        for (int nt = 0; nt < 8; nt++) {
            const float b0 = bl[ec + 8 * nt], b1 = bl[ec + 8 * nt + 1];
            const float v0 = fmaxf(acc[mt][nt][0] + b0, 0.f);
            const float v1 = fmaxf(acc[mt][nt][1] + b1, 0.f);
            const float v2 = fmaxf(acc[mt][nt][2] + b0, 0.f);
            const float v3 = fmaxf(acc[mt][nt][3] + b1, 0.f);
            const int r = er + mt * 16;
            const int c = ec + nt * 8;
            *(uint32_t*)(hbase + r * SROW + c * 2)       = h2u(__floats2half2_rn(v0, v1));
            *(uint32_t*)(hbase + (r + 8) * SROW + c * 2) = h2u(__floats2half2_rn(v2, v3));
        }
}

__device__ __forceinline__ void epi_final(const float acc[2][8][4],
                                          const float* __restrict__ bl,
                                          float* hf, int er, int ec) {
#pragma unroll
    for (int mt = 0; mt < 2; mt++)
#pragma unroll
        for (int nt = 0; nt < 8; nt++) {
            const float b0 = bl[ec + 8 * nt], b1 = bl[ec + 8 * nt + 1];
            const int r = er + mt * 16;
            const int c = ec + nt * 8;
            hf[r * F32_STRIDE + c]           = fmaxf(acc[mt][nt][0] + b0, 0.f);
            hf[r * F32_STRIDE + c + 1]       = fmaxf(acc[mt][nt][1] + b1, 0.f);
            hf[(r + 8) * F32_STRIDE + c]     = fmaxf(acc[mt][nt][2] + b0, 0.f);
            hf[(r + 8) * F32_STRIDE + c + 1] = fmaxf(acc[mt][nt][3] + b1, 0.f);
        }
}

// ============================================================================
// Main fused MLP kernel: 2 tiles x 128 rows, phase-interleaved MMA/epilogue
// ============================================================================
__global__ void __launch_bounds__(THREADS, 1)
mlp_main(const float* __restrict__ x, const float* __restrict__ b,
         const float* __restrict__ Wout, const float* __restrict__ bout,
         float* __restrict__ out) {
    extern __shared__ unsigned char smem[];
    const uint32_t sb = smem_to_u32(smem);
    const int tid = threadIdx.x;
    const int lane = tid & 31;
    const int wid = tid >> 5;
    const int wm = wid & 3;      // 4 m-warps x 32 rows
    const int wn = wid >> 2;     // 2 n-warps x 64 cols

    // ---- stage fixed tables ----
    {
        const float4* bs = (const float4*)b;
        float4* bd = (float4*)(smem + OFF_BIAS);
        bd[tid] = bs[tid];
        bd[tid + 256] = bs[tid + 256];
        if (tid < 64) ((float4*)(smem + OFF_WOUT))[tid] = ((const float4*)Wout)[tid];
        if (tid < 2)  ((float*)(smem + OFF_BOUT))[tid] = bout[tid];
    }

    // ---- kick W[0] copy ----
    load_w(sb + OFF_W, 0, tid);
    CP_COMMIT();

    // ---- prologue: x -> h0/h1 fp16 in SMEM ----
    {
        const float4* xs = (const float4*)(x + (size_t)blockIdx.x * ROWS * H);
#pragma unroll
        for (int i = 0; i < 32; i++) {
            const int idx = tid + i * THREADS;     // 0..8191
            const int r = idx >> 5, c = idx & 31;  // row 0..255, float4 idx
            const float4 v = xs[idx];
            unsigned char* hb = smem + (r < 128 ? OFF_H0 : OFF_H1);
            *(uint2*)(hb + (r & 127) * SROW + c * 8) =
                make_uint2(h2u(__floats2half2_rn(v.x, v.y)),
                           h2u(__floats2half2_rn(v.z, v.w)));
        }
    }

    // ---- per-thread ldmatrix address roles ----
    const int arow = (lane & 7) | (((lane >> 3) & 1) << 3);
    const int achk = lane >> 4;
    const uint32_t aoff = (uint32_t)((32 * wm + arow) * SROW + achk * 16);

    const int bg = lane >> 3;
    const int bn = ((bg >> 1) << 3) | (lane & 7);
    const int bchk = bg & 1;
    const uint32_t boff = (uint32_t)((64 * wn + bn) * SROW + bchk * 16);

    // epilogue roles
    const int er = 32 * wm + (lane >> 2);
    const int ec = 64 * wn + 2 * (lane & 3);

    const float* bias = (const float*)(smem + OFF_BIAS);

    float acc0[2][8][4], acc1[2][8][4];

#pragma unroll 1
    for (int l = 0; l < L; l++) {
        CP_WAIT0();              // W[l] resident (per-thread)
        __syncthreads();         // W + h0 writes visible; h1 reads (prev) done

        const uint32_t wb = sb + OFF_W + (uint32_t)(l & 1) * WTILE + boff;

        // ---- phase A: MMA tile0(l)  ||  epilogue tile1(l-1) ----
        mma_tile(acc0, sb + OFF_H0 + aoff, wb);
        if (l > 0)
            epi_h(acc1, bias + (l - 1) * H, smem + OFF_H1, er, ec);

        __syncthreads();         // h0 reads done; h1 writes visible

        // ---- phase B: prefetch W[l+1]; MMA tile1(l)  ||  epilogue tile0(l) ----
        if (l + 1 < L) {
            load_w(sb + OFF_W + (uint32_t)((l + 1) & 1) * WTILE, l + 1, tid);
            CP_COMMIT();
            mma_tile(acc1, sb + OFF_H1 + aoff, wb);
            epi_h(acc0, bias + l * H, smem + OFF_H0, er, ec);
        } else {
            mma_tile(acc1, sb + OFF_H1 + aoff, wb);
            __syncthreads();     // retire all h1/W reads before fp32 overwrite
            epi_final(acc0, bias + l * H, (float*)(smem + OFF_H0), er, ec);
            epi_final(acc1, bias + l * H, (float*)(smem + OFF_W),  er, ec);
        }
    }

    __syncthreads();

    // ---- final projection: relu_h[256] @ Wout.T + bout ----
    {
        const float* hf = (const float*)(smem + (tid < 128 ? OFF_H0 : OFF_W))
                        + (tid & 127) * F32_STRIDE;
        const float* wo = (const float*)(smem + OFF_WOUT);
        const float* bo = (const float*)(smem + OFF_BOUT);
        float o0 = bo[0], o1 = bo[1];
#pragma unroll
        for (int k = 0; k < H; k++) {
            const float v = hf[k];
            o0 = fmaf(v, wo[k], o0);
            o1 = fmaf(v, wo[H + k], o1);
        }
        ((float2*)out)[(size_t)blockIdx.x * ROWS + tid] = make_float2(o0, o1);
    }
}

// ============================================================================
// Launch
// ============================================================================
extern "C" void kernel_launch(void* const* d_in, const int* in_sizes, int n_in,
                              void* d_out, int out_size) {
    const float* x    = (const float*)d_in[0];
    const float* W    = (const float*)d_in[1];
    const float* b    = (const float*)d_in[2];
    const float* Wout = (const float*)d_in[3];
    const float* bout = (const float*)d_in[4];
    float* out = (float*)d_out;

    prep_w_kernel<<<L, 256>>>(W);

    cudaFuncSetAttribute(mlp_main, cudaFuncAttributeMaxDynamicSharedMemorySize, SMEM_BYTES);
    mlp_main<<<NROWS / ROWS, THREADS, SMEM_BYTES>>>(x, b, Wout, bout, out);
}

// round 6
// speedup vs baseline: 2.7579x; 1.1358x over previous
#include <cuda_runtime.h>
#include <cuda_fp16.h>
#include <cstdint>
#include <cstring>

// ============================================================================
// Problem constants
// ============================================================================
static constexpr int NROWS   = 1048576;
static constexpr int H       = 128;
static constexpr int L       = 16;
static constexpr int THREADS = 256;
static constexpr int ROWS    = 256;    // per CTA: two 128-row tiles

// Padded row: 128 halves + 8 pad = 272 bytes -> conflict-free ldmatrix.
static constexpr int SROW  = 272;
static constexpr int WTILE = 128 * SROW;        // one 128x128 fp16 matrix: 34816 B

// SMEM layout (byte offsets) -- sized for 2 CTAs/SM
static constexpr int OFF_H0   = 0;                       // tile0 h (fp16)
static constexpr int OFF_H1   = OFF_H0 + WTILE;          // 34816 tile1 h
static constexpr int OFF_W    = OFF_H1 + WTILE;          // 69632 single W buffer
static constexpr int OFF_BIAS = OFF_W + WTILE;           // 104448
static constexpr int OFF_WOUT = OFF_BIAS + L * H * 4;    // 112640
static constexpr int OFF_BOUT = OFF_WOUT + 2 * H * 4;    // 113664
static constexpr int SMEM_BYTES = OFF_BOUT + 16;         // 113680 (~111 KB)

// Plain fp16 W image, padded [n][k] rows (row n: W[n][k] at n*SROW + 2k)
__device__ __align__(128) unsigned char g_w[(size_t)L * WTILE];

// ============================================================================
// PTX helpers
// ============================================================================
__device__ __forceinline__ uint32_t smem_to_u32(const void* p) {
    uint32_t a;
    asm("{ .reg .u64 t; cvta.to.shared.u64 t, %1; cvt.u32.u64 %0, t; }"
        : "=r"(a) : "l"(p));
    return a;
}

#define LDSM_X4(r, addr) \
    asm volatile("ldmatrix.sync.aligned.m8n8.x4.shared.b16 {%0,%1,%2,%3}, [%4];" \
        : "=r"((r)[0]), "=r"((r)[1]), "=r"((r)[2]), "=r"((r)[3]) : "r"(addr))

#define MMA16816(c, a, b0, b1) \
    asm volatile("mma.sync.aligned.m16n8k16.row.col.f32.f16.f16.f32 " \
        "{%0,%1,%2,%3}, {%4,%5,%6,%7}, {%8,%9}, {%0,%1,%2,%3};" \
        : "+f"((c)[0]), "+f"((c)[1]), "+f"((c)[2]), "+f"((c)[3]) \
        : "r"((a)[0]), "r"((a)[1]), "r"((a)[2]), "r"((a)[3]), "r"(b0), "r"(b1))

__device__ __forceinline__ void cp16(uint32_t dst, const void* src) {
    asm volatile("cp.async.cg.shared.global [%0], [%1], 16;" :: "r"(dst), "l"(src));
}
#define CP_COMMIT() asm volatile("cp.async.commit_group;" ::: "memory")
#define CP_WAIT0()  asm volatile("cp.async.wait_group 0;" ::: "memory")

__device__ __forceinline__ uint32_t h2u(__half2 h) {
    uint32_t u; memcpy(&u, &h, 4); return u;
}

// ============================================================================
// Prep kernel: W -> fp16, padded [n][k] layout per layer
// ============================================================================
__global__ void prep_w_kernel(const float* __restrict__ W) {
    const int l = blockIdx.x;
    const float* Wl = W + (size_t)l * H * H;
    unsigned char* dst = g_w + (size_t)l * WTILE;
    for (int i = threadIdx.x; i < H * H; i += blockDim.x) {
        const int n = i >> 7, k = i & 127;
        *(__half*)(dst + n * SROW + 2 * k) = __float2half_rn(Wl[i]);
    }
}

// issue cp.async for one layer's W tile (34816 B = 2176 x 16B)
__device__ __forceinline__ void load_w(uint32_t dst_smem, int l, int tid) {
    const unsigned char* src = g_w + (size_t)l * WTILE;
#pragma unroll
    for (int i = 0; i < 9; i++) {
        const int idx = tid + i * THREADS;
        if (idx < WTILE / 16) cp16(dst_smem + idx * 16, src + idx * 16);
    }
}

// ============================================================================
// MMA for one 128-row tile: acc = h @ W_l^T   (single fp16 pass, fp32 acc)
// ============================================================================
__device__ __forceinline__ void mma_tile(float acc[2][8][4], uint32_t ha, uint32_t wb) {
#pragma unroll
    for (int mt = 0; mt < 2; mt++)
#pragma unroll
        for (int nt = 0; nt < 8; nt++)
#pragma unroll
            for (int q = 0; q < 4; q++) acc[mt][nt][q] = 0.f;

#pragma unroll
    for (int ks = 0; ks < 8; ks++) {
        const uint32_t kb = ks * 32;
        uint32_t af[2][4], bf[4][4];
#pragma unroll
        for (int mt = 0; mt < 2; mt++)
            LDSM_X4(af[mt], ha + mt * (16 * SROW) + kb);
#pragma unroll
        for (int ng = 0; ng < 4; ng++)
            LDSM_X4(bf[ng], wb + ng * (16 * SROW) + kb);

#pragma unroll
        for (int mt = 0; mt < 2; mt++)
#pragma unroll
            for (int ng = 0; ng < 4; ng++) {
                MMA16816(acc[mt][2 * ng],     af[mt], bf[ng][0], bf[ng][1]);
                MMA16816(acc[mt][2 * ng + 1], af[mt], bf[ng][2], bf[ng][3]);
            }
    }
}

// ============================================================================
// Epilogue: acc -> bias + relu -> fp16 h tile
// ============================================================================
__device__ __forceinline__ void epi_h(const float acc[2][8][4],
                                      const float* __restrict__ bl,
                                      unsigned char* hbase, int er, int ec) {
#pragma unroll
    for (int mt = 0; mt < 2; mt++)
#pragma unroll
        for (int nt = 0; nt < 8; nt++) {
            const float b0 = bl[ec + 8 * nt], b1 = bl[ec + 8 * nt + 1];
            const float v0 = fmaxf(acc[mt][nt][0] + b0, 0.f);
            const float v1 = fmaxf(acc[mt][nt][1] + b1, 0.f);
            const float v2 = fmaxf(acc[mt][nt][2] + b0, 0.f);
            const float v3 = fmaxf(acc[mt][nt][3] + b1, 0.f);
            const int r = er + mt * 16;
            const int c = ec + nt * 8;
            *(uint32_t*)(hbase + r * SROW + c * 2)       = h2u(__floats2half2_rn(v0, v1));
            *(uint32_t*)(hbase + (r + 8) * SROW + c * 2) = h2u(__floats2half2_rn(v2, v3));
        }
}

// ============================================================================
// Main fused MLP kernel: 2 tiles x 128 rows, occupancy-2 overlap
// ============================================================================
__global__ void __launch_bounds__(THREADS, 2)
mlp_main(const float* __restrict__ x, const float* __restrict__ b,
         const float* __restrict__ Wout, const float* __restrict__ bout,
         float* __restrict__ out) {
    extern __shared__ unsigned char smem[];
    const uint32_t sb = smem_to_u32(smem);
    const int tid = threadIdx.x;
    const int lane = tid & 31;
    const int wid = tid >> 5;
    const int wm = wid & 3;      // 4 m-warps x 32 rows
    const int wn = wid >> 2;     // 2 n-warps x 64 cols

    // ---- stage fixed tables ----
    {
        const float4* bs = (const float4*)b;
        float4* bd = (float4*)(smem + OFF_BIAS);
        bd[tid] = bs[tid];
        bd[tid + 256] = bs[tid + 256];
        if (tid < 64) ((float4*)(smem + OFF_WOUT))[tid] = ((const float4*)Wout)[tid];
        if (tid < 2)  ((float*)(smem + OFF_BOUT))[tid] = bout[tid];
    }

    // ---- kick W[0] copy ----
    load_w(sb + OFF_W, 0, tid);
    CP_COMMIT();

    // ---- prologue: x -> h0/h1 fp16 in SMEM ----
    {
        const float4* xs = (const float4*)(x + (size_t)blockIdx.x * ROWS * H);
#pragma unroll
        for (int i = 0; i < 32; i++) {
            const int idx = tid + i * THREADS;     // 0..8191
            const int r = idx >> 5, c = idx & 31;  // row 0..255, float4 idx
            const float4 v = xs[idx];
            unsigned char* hb = smem + (r < 128 ? OFF_H0 : OFF_H1);
            *(uint2*)(hb + (r & 127) * SROW + c * 8) =
                make_uint2(h2u(__floats2half2_rn(v.x, v.y)),
                           h2u(__floats2half2_rn(v.z, v.w)));
        }
    }

    // ---- per-thread ldmatrix address roles ----
    const int arow = (lane & 7) | (((lane >> 3) & 1) << 3);
    const int achk = lane >> 4;
    const uint32_t aoff = (uint32_t)((32 * wm + arow) * SROW + achk * 16);

    const int bg = lane >> 3;
    const int bn = ((bg >> 1) << 3) | (lane & 7);
    const int bchk = bg & 1;
    const uint32_t boff = (uint32_t)((64 * wn + bn) * SROW + bchk * 16);

    // epilogue roles
    const int er = 32 * wm + (lane >> 2);
    const int ec = 64 * wn + 2 * (lane & 3);

    const float* bias = (const float*)(smem + OFF_BIAS);
    const uint32_t wb = sb + OFF_W + boff;

    float acc[2][8][4];

#pragma unroll 1
    for (int l = 0; l < L; l++) {
        CP_WAIT0();              // W[l] resident (per-thread)
        __syncthreads();         // W + h writes visible across CTA

        // ---- tile0: MMA then epilogue ----
        mma_tile(acc, sb + OFF_H0 + aoff, wb);
        __syncthreads();         // all warps' h0 reads done
        epi_h(acc, bias + l * H, smem + OFF_H0, er, ec);

        // ---- tile1: MMA then (prefetch W[l+1]) epilogue ----
        mma_tile(acc, sb + OFF_H1 + aoff, wb);
        __syncthreads();         // all h1 reads + all W[l] reads done
        if (l + 1 < L) {
            load_w(sb + OFF_W, l + 1, tid);
            CP_COMMIT();
        }
        epi_h(acc, bias + l * H, smem + OFF_H1, er, ec);
    }

    __syncthreads();

    // ---- final projection: relu_h[256] (fp16) @ Wout.T + bout ----
    {
        const unsigned char* hb = smem + (tid < 128 ? OFF_H0 : OFF_H1);
        const uint2* hrow = (const uint2*)(hb + (tid & 127) * SROW);
        const float* wo = (const float*)(smem + OFF_WOUT);
        const float* bo = (const float*)(smem + OFF_BOUT);
        float o0 = bo[0], o1 = bo[1];
#pragma unroll
        for (int q = 0; q < 32; q++) {
            const uint2 u = hrow[q];
            __half2 p0, p1;
            memcpy(&p0, &u.x, 4);
            memcpy(&p1, &u.y, 4);
            const float2 f0 = __half22float2(p0);
            const float2 f1 = __half22float2(p1);
            const int k = q * 4;
            o0 = fmaf(f0.x, wo[k],     o0); o1 = fmaf(f0.x, wo[H + k],     o1);
            o0 = fmaf(f0.y, wo[k + 1], o0); o1 = fmaf(f0.y, wo[H + k + 1], o1);
            o0 = fmaf(f1.x, wo[k + 2], o0); o1 = fmaf(f1.x, wo[H + k + 2], o1);
            o0 = fmaf(f1.y, wo[k + 3], o0); o1 = fmaf(f1.y, wo[H + k + 3], o1);
        }
        ((float2*)out)[(size_t)blockIdx.x * ROWS + tid] = make_float2(o0, o1);
    }
}

// ============================================================================
// Launch
// ============================================================================
extern "C" void kernel_launch(void* const* d_in, const int* in_sizes, int n_in,
                              void* d_out, int out_size) {
    const float* x    = (const float*)d_in[0];
    const float* W    = (const float*)d_in[1];
    const float* b    = (const float*)d_in[2];
    const float* Wout = (const float*)d_in[3];
    const float* bout = (const float*)d_in[4];
    float* out = (float*)d_out;

    prep_w_kernel<<<L, 256>>>(W);

    cudaFuncSetAttribute(mlp_main, cudaFuncAttributeMaxDynamicSharedMemorySize, SMEM_BYTES);
    mlp_main<<<NROWS / ROWS, THREADS, SMEM_BYTES>>>(x, b, Wout, bout, out);
}